// round 16
// baseline (speedup 1.0000x reference)
#include <cuda_runtime.h>
#include <cuda_fp16.h>
#include <cstdint>

#define S_LEN 2304
#define C_DIM 1024
#define NH    16
#define HD    64
#define BATCH 2

// ---------------- scratch (all single fp16) -----------------------------------
__device__ __half g_Wq[(size_t)3 * C_DIM * C_DIM];
__device__ __half g_Wo[(size_t)C_DIM * C_DIM];
__device__ __half g_x[(size_t)BATCH * S_LEN * C_DIM];      // x^T tokens-major
__device__ __half g_z[(size_t)BATCH * S_LEN * C_DIM];
__device__ __half g_q[(size_t)BATCH * NH * S_LEN * HD];    // pre-scaled 1/8*log2e
__device__ __half g_k[(size_t)BATCH * NH * S_LEN * HD];
__device__ __half g_v[(size_t)BATCH * NH * S_LEN * HD];

// ---------------- helpers ----------------------------------------------------
__device__ __forceinline__ uint32_t smem_u32(const void* p) {
    uint32_t a;
    asm("{ .reg .u64 t; cvta.to.shared.u64 t, %1; cvt.u32.u64 %0, t; }" : "=r"(a) : "l"(p));
    return a;
}
__device__ __forceinline__ void ldsm4(uint32_t* r, uint32_t addr) {
    asm volatile("ldmatrix.sync.aligned.m8n8.x4.shared.b16 {%0,%1,%2,%3}, [%4];"
                 : "=r"(r[0]), "=r"(r[1]), "=r"(r[2]), "=r"(r[3]) : "r"(addr));
}
__device__ __forceinline__ void ldsm4t(uint32_t* r, uint32_t addr) {
    asm volatile("ldmatrix.sync.aligned.m8n8.x4.trans.shared.b16 {%0,%1,%2,%3}, [%4];"
                 : "=r"(r[0]), "=r"(r[1]), "=r"(r[2]), "=r"(r[3]) : "r"(addr));
}
__device__ __forceinline__ void mma_f16(float* c, const uint32_t* a,
                                        uint32_t b0, uint32_t b1) {
    asm volatile(
        "mma.sync.aligned.m16n8k16.row.col.f32.f16.f16.f32 "
        "{%0,%1,%2,%3}, {%4,%5,%6,%7}, {%8,%9}, {%0,%1,%2,%3};"
        : "+f"(c[0]), "+f"(c[1]), "+f"(c[2]), "+f"(c[3])
        : "r"(a[0]), "r"(a[1]), "r"(a[2]), "r"(a[3]), "r"(b0), "r"(b1));
}
#define CP16(dst, src) asm volatile("cp.async.cg.shared.global [%0], [%1], 16;" :: "r"(dst), "l"(src))
#define CP_COMMIT()    asm volatile("cp.async.commit_group;" ::: "memory")
#define CP_WAIT0()     asm volatile("cp.async.wait_group 0;" ::: "memory")
#define CP_WAIT1()     asm volatile("cp.async.wait_group 1;" ::: "memory")
#define CP_WAIT2()     asm volatile("cp.async.wait_group 2;" ::: "memory")

__device__ __forceinline__ uint32_t pack2h(float a, float b) {
    __half2 h = __floats2half2_rn(a, b);
    return *reinterpret_cast<uint32_t*>(&h);
}
__device__ __forceinline__ uint32_t h2ex2(uint32_t x) {
    uint32_t d;
    asm("ex2.approx.f16x2 %0, %1;" : "=r"(d) : "r"(x));
    return d;
}

#define LOG2E 1.4426950408889634f
#define MASK2 14426.950408889634f   // 10000 * log2(e)
#define ONES2 0x3C003C00u           // half2(1.0, 1.0)

// ---------------- prep kernels ----------------------------------------------
__global__ void tohalf2_kernel(const float* __restrict__ s0, __half* __restrict__ d0, int n0,
                               const float* __restrict__ s1, __half* __restrict__ d1, int n1) {
    int i = blockIdx.x * 256 + threadIdx.x;
    const float* src; __half* dst;
    if (i < n0) { src = s0; dst = d0; }
    else if (i < n0 + n1) { i -= n0; src = s1; dst = d1; }
    else return;
    float4 v = reinterpret_cast<const float4*>(src)[i];
    *reinterpret_cast<uint32_t*>(dst + i * 4)     = pack2h(v.x, v.y);
    *reinterpret_cast<uint32_t*>(dst + i * 4 + 2) = pack2h(v.z, v.w);
}

__global__ void xpose_half(const float* __restrict__ x) {
    __shared__ float tile[32][33];
    int b = blockIdx.z, t0 = blockIdx.x * 32, c0 = blockIdx.y * 32;
    int tx = threadIdx.x, ty = threadIdx.y;
    for (int i = ty; i < 32; i += 8)
        tile[i][tx] = x[((size_t)b * C_DIM + c0 + i) * S_LEN + t0 + tx];
    __syncthreads();
    for (int i = ty; i < 32; i += 8) {
        size_t oi = ((size_t)b * S_LEN + t0 + i) * C_DIM + c0 + tx;
        g_x[oi] = __float2half_rn(tile[tx][i]);
    }
}

// ---------------- mma.sync GEMM core: 256x128 tile, 512 thr, 4-stage ring ------
#define GP 72                          // pitch in halfs (144 B rows)
#define ABYTES (256 * 144)             // 36864
#define BBYTES (128 * 144)             // 18432
#define STBYTES (ABYTES + BBYTES)      // 55296

__device__ __forceinline__ void fill_async(
    uint32_t stage_s, int tid, int k0,
    const __half* A, const __half* B) {
#pragma unroll
    for (int i = tid; i < 2048; i += 512) {
        int r = i >> 3, c = (i & 7) * 16;
        CP16(stage_s + r * 144 + c, (const char*)(A + (size_t)r * C_DIM + k0) + c);
    }
#pragma unroll
    for (int i = tid; i < 1024; i += 512) {
        int r = i >> 3, c = (i & 7) * 16;
        CP16(stage_s + ABYTES + r * 144 + c, (const char*)(B + (size_t)r * C_DIM + k0) + c);
    }
    CP_COMMIT();
}

__device__ __forceinline__ void compute_stage(
    uint32_t st, int lane, int wm, int wn, float acc[4][4][4]) {
    uint32_t A_s = st, B_s = st + ABYTES;
    int ar = lane & 15, ach = (lane >> 4) * 8;
    int bg = lane >> 3, br = lane & 7;
    int brow = wn * 32 + (bg >> 1) * 8 + br;
    int bch = (bg & 1) * 8;
#pragma unroll
    for (int ks = 0; ks < 4; ks++) {
        uint32_t a[4][4], bb[2][4];
#pragma unroll
        for (int mi = 0; mi < 4; mi++)
            ldsm4(a[mi], A_s + ((wm * 64 + mi * 16 + ar) * GP + ks * 16 + ach) * 2);
#pragma unroll
        for (int nj = 0; nj < 2; nj++)
            ldsm4(bb[nj], B_s + ((brow + nj * 16) * GP + ks * 16 + bch) * 2);
#pragma unroll
        for (int mi = 0; mi < 4; mi++)
#pragma unroll
            for (int nj = 0; nj < 2; nj++) {
                mma_f16(acc[mi][nj * 2],     a[mi], bb[nj][0], bb[nj][1]);
                mma_f16(acc[mi][nj * 2 + 1], a[mi], bb[nj][2], bb[nj][3]);
            }
    }
}

__device__ __forceinline__ void gemm_body(
    uint32_t smb, int tid, float acc[4][4][4],
    const __half* A, const __half* B) {
    int lane = tid & 31, wid = tid >> 5;
    int wm = wid & 3, wn = wid >> 2;
    const int NC = C_DIM / 64;  // 16
    fill_async(smb, tid, 0, A, B);
    fill_async(smb + STBYTES, tid, 64, A, B);
    for (int ch = 0; ch < NC; ch++) {
        if (ch + 2 < NC) {
            fill_async(smb + ((ch + 2) & 3) * STBYTES, tid, (ch + 2) * 64, A, B);
            CP_WAIT2();
        } else if (ch + 2 == NC) {
            CP_WAIT1();
        } else {
            CP_WAIT0();
        }
        __syncthreads();
        compute_stage(smb + (ch & 3) * STBYTES, lane, wm, wn, acc);
    }
}

// ---------------- QKV projection (M = 256 tokens, N = 128 channels) ------------
__global__ __launch_bounds__(512, 1)
void qkv_tc(const float* __restrict__ bias) {
    extern __shared__ char sm[];
    uint32_t smb = smem_u32(sm);
    int tid = threadIdx.x;
    int b = blockIdx.z, n0 = blockIdx.x * 256, m0 = blockIdx.y * 128;

    float acc[4][4][4];
#pragma unroll
    for (int mi = 0; mi < 4; mi++)
#pragma unroll
        for (int ni = 0; ni < 4; ni++)
#pragma unroll
            for (int r = 0; r < 4; r++) acc[mi][ni][r] = 0.0f;

    gemm_body(smb, tid, acc,
              g_x + ((size_t)b * S_LEN + n0) * C_DIM,
              g_Wq + (size_t)m0 * C_DIM);

    int lane = tid & 31, wid = tid >> 5;
    int wm = wid & 3, wn = wid >> 2;
    int tc = lane & 3;
    int which = m0 >> 10;
    __half* dstb = (which == 0) ? g_q : (which == 1) ? g_k : g_v;
    float scale = (which == 0) ? (0.125f * LOG2E) : 1.0f;   // q in base-2 domain
    int mch0 = m0 + wn * 32;
    int head = (mch0 >> 6) & 15;
    int d0 = mch0 & 63;
    __half* base = dstb + ((size_t)(b * NH + head)) * S_LEN * HD;

    float bv0[4], bv1[4];
#pragma unroll
    for (int ni = 0; ni < 4; ni++) {
        bv0[ni] = bias[mch0 + ni * 8 + tc * 2];
        bv1[ni] = bias[mch0 + ni * 8 + tc * 2 + 1];
    }
#pragma unroll
    for (int mi = 0; mi < 4; mi++) {
#pragma unroll
        for (int rg = 0; rg < 2; rg++) {
            int t = n0 + wm * 64 + mi * 16 + (lane >> 2) + rg * 8;
            __half* rowp = base + (size_t)t * HD + d0 + tc * 2;
#pragma unroll
            for (int ni = 0; ni < 4; ni++) {
                uint32_t u = pack2h((acc[mi][ni][rg * 2 + 0] + bv0[ni]) * scale,
                                    (acc[mi][ni][rg * 2 + 1] + bv1[ni]) * scale);
                *reinterpret_cast<uint32_t*>(rowp + ni * 8) = u;
            }
        }
    }
}

// ---------------- Output projection (M = 256 co, N = 128 tokens) ---------------
__global__ __launch_bounds__(512, 1)
void out_tc(const float* __restrict__ bo, float* __restrict__ out) {
    extern __shared__ char sm[];
    uint32_t smb = smem_u32(sm);
    int tid = threadIdx.x;
    int b = blockIdx.z, m0 = blockIdx.y * 256, n0 = blockIdx.x * 128;

    float acc[4][4][4];
#pragma unroll
    for (int mi = 0; mi < 4; mi++)
#pragma unroll
        for (int ni = 0; ni < 4; ni++)
#pragma unroll
            for (int r = 0; r < 4; r++) acc[mi][ni][r] = 0.0f;

    gemm_body(smb, tid, acc,
              g_Wo + (size_t)m0 * C_DIM,
              g_z + ((size_t)b * S_LEN + n0) * C_DIM);

    int lane = tid & 31, wid = tid >> 5;
    int wm = wid & 3, wn = wid >> 2;
    int tc = lane & 3;
#pragma unroll
    for (int mi = 0; mi < 4; mi++) {
#pragma unroll
        for (int rg = 0; rg < 2; rg++) {
            int m = m0 + wm * 64 + mi * 16 + (lane >> 2) + rg * 8;
            float bv = bo[m];
            float* dst = out + ((size_t)b * C_DIM + m) * S_LEN;
#pragma unroll
            for (int ni = 0; ni < 4; ni++) {
                int t = n0 + wn * 32 + ni * 8 + tc * 2;
                float2 v = {acc[mi][ni][rg * 2 + 0] + bv,
                            acc[mi][ni][rg * 2 + 1] + bv};
                *reinterpret_cast<float2*>(dst + t) = v;
            }
        }
    }
}

// ---------------- Flash attention (Q frags hoisted to registers) ----------------
#define AP 72
#define QBYTES   18432
#define KVTILE   9216
#define KVBUF    18432

__device__ __forceinline__ void fill_kv(
    uint32_t dst, int tid, int s0, const __half* k, const __half* v) {
#pragma unroll
    for (int i = tid; i < 512; i += 256) {
        int r = i >> 3, c = (i & 7) * 16;
        uint32_t so = r * 144 + c;
        size_t go = (size_t)(s0 + r) * HD;
        CP16(dst + so,          (const char*)(k + go) + c);
        CP16(dst + KVTILE + so, (const char*)(v + go) + c);
    }
    CP_COMMIT();
}

__global__ __launch_bounds__(256, 2)
void attn_tc() {
    extern __shared__ char sm[];
    uint32_t smb = smem_u32(sm);
    uint32_t Q_s  = smb;
    uint32_t KV_s = smb + QBYTES;

    int head = blockIdx.y, b = blockIdx.z;
    int tid = threadIdx.x, lane = tid & 31, wid = tid >> 5;
    int r0w = wid * 16;
    int g = lane >> 2, tc = lane & 3;

    size_t base = ((size_t)(b * NH + head)) * S_LEN * HD;
    const __half* qp = g_q + base;
    const __half* kp = g_k + base;
    const __half* vp = g_v + base;

    int ar = lane & 15, ach = (lane >> 4) * 8;
    int bg = lane >> 3, br = lane & 7;
    int krow_off = ((bg >> 1) * 8 + br) * AP + (bg & 1) * 8;
    int vrow = ((lane >> 3) & 1) * 8 + (lane & 7);
    int vcol = (lane >> 4) * 8;

    for (int rep = 0; rep < 2; rep++) {
        int qt = rep == 0 ? (17 - (int)blockIdx.x) : (int)blockIdx.x;
        int q0 = qt * 128;

#pragma unroll
        for (int i = tid; i < 1024; i += 256) {
            int r = i >> 3, c = (i & 7) * 16;
            CP16(Q_s + r * 144 + c, (const char*)(qp + (size_t)(q0 + r) * HD) + c);
        }
        CP_COMMIT();

        float o[8][4] = {};
        float mA = -1e30f, mB = -1e30f, lA = 0.0f, lB = 0.0f;
        uint32_t qf[4][4];   // persistent Q fragments for this rep

        int nkt = 2 * qt + 2;
        fill_kv(KV_s, tid, 0, kp, vp);
        fill_kv(KV_s + KVBUF, tid, 64, kp, vp);
        for (int kt = 0; kt < nkt; kt++) {
            int c0 = kt * 64;
            if (kt + 2 < nkt) {
                fill_kv(KV_s + ((kt + 2) & 3) * KVBUF, tid, (kt + 2) * 64, kp, vp);
                CP_WAIT2();
            } else if (kt + 2 == nkt) {
                CP_WAIT1();
            } else {
                CP_WAIT0();
            }
            __syncthreads();
            uint32_t K_s = KV_s + (kt & 3) * KVBUF;
            uint32_t V_s = K_s + KVTILE;

            if (kt == 0) {   // Q group retired (only <=2 newer groups pending)
#pragma unroll
                for (int kc = 0; kc < 4; kc++)
                    ldsm4(qf[kc], Q_s + ((r0w + ar) * AP + kc * 16 + ach) * 2);
            }

            // ---- S = Q K^T (log2 units) ----
            float s[8][4] = {};
#pragma unroll
            for (int kc = 0; kc < 4; kc++) {
#pragma unroll
                for (int np = 0; np < 4; np++) {
                    uint32_t kk[4];
                    ldsm4(kk, K_s + (np * 16 * AP + kc * 16 + krow_off) * 2);
                    mma_f16(s[np * 2],     qf[kc], kk[0], kk[1]);
                    mma_f16(s[np * 2 + 1], qf[kc], kk[2], kk[3]);
                }
            }

            // ---- mask (register domain, base-2) ----
            if (c0 + 63 > q0 + r0w) {
                int rowA = q0 + r0w + g, rowB = rowA + 8;
#pragma unroll
                for (int nf = 0; nf < 8; nf++) {
                    int col = c0 + nf * 8 + tc * 2;
                    if (col     > rowA) s[nf][0] -= MASK2;
                    if (col + 1 > rowA) s[nf][1] -= MASK2;
                    if (col     > rowB) s[nf][2] -= MASK2;
                    if (col + 1 > rowB) s[nf][3] -= MASK2;
                }
            }

            // ---- running max (quad shuffles) ----
            float pmA = -1e30f, pmB = -1e30f;
#pragma unroll
            for (int nf = 0; nf < 8; nf++) {
                pmA = fmaxf(pmA, fmaxf(s[nf][0], s[nf][1]));
                pmB = fmaxf(pmB, fmaxf(s[nf][2], s[nf][3]));
            }
            pmA = fmaxf(pmA, __shfl_xor_sync(0xffffffffu, pmA, 1));
            pmA = fmaxf(pmA, __shfl_xor_sync(0xffffffffu, pmA, 2));
            pmB = fmaxf(pmB, __shfl_xor_sync(0xffffffffu, pmB, 1));
            pmB = fmaxf(pmB, __shfl_xor_sync(0xffffffffu, pmB, 2));
            float mnA = fmaxf(mA, pmA), mnB = fmaxf(mB, pmB);

            // ---- alpha rescale (skipped when running max unchanged) ----
            float alA = 1.0f, alB = 1.0f;
            if (__any_sync(0xffffffffu, (mnA > mA) || (mnB > mB))) {
                alA = exp2f(mA - mnA);
                alB = exp2f(mB - mnB);
#pragma unroll
                for (int nf = 0; nf < 8; nf++) {
                    o[nf][0] *= alA; o[nf][1] *= alA;
                    o[nf][2] *= alB; o[nf][3] *= alB;
                }
            }
            mA = mnA; mB = mnB;

            // ---- P = ex2(S - m) in fp16x2 regs ----
            uint32_t pu[8][2];
#pragma unroll
            for (int nf = 0; nf < 8; nf++) {
                pu[nf][0] = h2ex2(pack2h(s[nf][0] - mnA, s[nf][1] - mnA));
                pu[nf][1] = h2ex2(pack2h(s[nf][2] - mnB, s[nf][3] - mnB));
            }

            // ---- l-sum via ones-MMA + O += P V ----
            float lf[4] = {0.0f, 0.0f, 0.0f, 0.0f};
#pragma unroll
            for (int kc = 0; kc < 4; kc++) {
                uint32_t ph[4];
                ph[0] = pu[2 * kc][0];
                ph[1] = pu[2 * kc][1];
                ph[2] = pu[2 * kc + 1][0];
                ph[3] = pu[2 * kc + 1][1];
                mma_f16(lf, ph, ONES2, ONES2);   // row-sums of P (quad-reduced)
#pragma unroll
                for (int np = 0; np < 4; np++) {
                    uint32_t vv[4];
                    ldsm4t(vv, V_s + ((kc * 16 + vrow) * AP + np * 16 + vcol) * 2);
                    mma_f16(o[np * 2],     ph, vv[0], vv[1]);
                    mma_f16(o[np * 2 + 1], ph, vv[2], vv[3]);
                }
            }
            lA = lA * alA + lf[0];
            lB = lB * alB + lf[2];
        }

        // ---- epilogue: z = O / l, fp16 ----
        float liA = 1.0f / lA, liB = 1.0f / lB;
        int tA = q0 + r0w + g, tB = tA + 8;
#pragma unroll
        for (int nf = 0; nf < 8; nf++) {
            int d = nf * 8 + tc * 2;
            size_t ziA = ((size_t)b * S_LEN + tA) * C_DIM + head * HD + d;
            size_t ziB = ((size_t)b * S_LEN + tB) * C_DIM + head * HD + d;
            *reinterpret_cast<uint32_t*>(g_z + ziA) = pack2h(o[nf][0] * liA, o[nf][1] * liA);
            *reinterpret_cast<uint32_t*>(g_z + ziB) = pack2h(o[nf][2] * liB, o[nf][3] * liB);
        }
        __syncthreads();
    }
}

// ---------------------------------------------------------------------------

extern "C" void kernel_launch(void* const* d_in, const int* in_sizes, int n_in,
                              void* d_out, int out_size) {
    const float* x    = (const float*)d_in[0];
    const float* Wqkv = (const float*)d_in[1];
    const float* bqkv = (const float*)d_in[2];
    const float* Wo   = (const float*)d_in[3];
    const float* bo   = (const float*)d_in[4];
    float* out = (float*)d_out;

    __half *wq, *wo;
    cudaGetSymbolAddress((void**)&wq, g_Wq);
    cudaGetSymbolAddress((void**)&wo, g_Wo);

    int nq4 = 3 * C_DIM * C_DIM / 4;
    int no4 = C_DIM * C_DIM / 4;
    tohalf2_kernel<<<(nq4 + no4 + 255) / 256, 256>>>(Wqkv, wq, nq4, Wo, wo, no4);

    dim3 gT(S_LEN / 32, C_DIM / 32, BATCH);
    xpose_half<<<gT, dim3(32, 8)>>>(x);

    size_t gsmem = 4 * STBYTES;   // 221184
    cudaFuncSetAttribute(qkv_tc, cudaFuncAttributeMaxDynamicSharedMemorySize, (int)gsmem);
    cudaFuncSetAttribute(out_tc, cudaFuncAttributeMaxDynamicSharedMemorySize, (int)gsmem);

    dim3 gA(S_LEN / 256, 3 * C_DIM / 128, BATCH);   // (9, 24, 2)
    qkv_tc<<<gA, 512, gsmem>>>(bqkv);

    size_t asmem = QBYTES + 4 * KVBUF;   // 92160
    cudaFuncSetAttribute(attn_tc, cudaFuncAttributeMaxDynamicSharedMemorySize, (int)asmem);
    dim3 gB(9, NH, BATCH);
    attn_tc<<<gB, 256, asmem>>>();

    dim3 gC(S_LEN / 128, C_DIM / 256, BATCH);       // (18, 4, 2)
    out_tc<<<gC, 512, gsmem>>>(bo, out);
}

// round 17
// speedup vs baseline: 1.0234x; 1.0234x over previous
#include <cuda_runtime.h>
#include <cuda_fp16.h>
#include <cstdint>

#define S_LEN 2304
#define C_DIM 1024
#define NH    16
#define HD    64
#define BATCH 2

// ---------------- scratch (all single fp16) -----------------------------------
__device__ __half g_Wq[(size_t)3 * C_DIM * C_DIM];
__device__ __half g_Wo[(size_t)C_DIM * C_DIM];
__device__ __half g_x[(size_t)BATCH * S_LEN * C_DIM];      // x^T tokens-major
__device__ __half g_z[(size_t)BATCH * S_LEN * C_DIM];
__device__ __half g_q[(size_t)BATCH * NH * S_LEN * HD];    // pre-scaled 1/8*log2e
__device__ __half g_k[(size_t)BATCH * NH * S_LEN * HD];
__device__ __half g_v[(size_t)BATCH * NH * S_LEN * HD];

// ---------------- helpers ----------------------------------------------------
__device__ __forceinline__ uint32_t smem_u32(const void* p) {
    uint32_t a;
    asm("{ .reg .u64 t; cvta.to.shared.u64 t, %1; cvt.u32.u64 %0, t; }" : "=r"(a) : "l"(p));
    return a;
}
__device__ __forceinline__ void ldsm4(uint32_t* r, uint32_t addr) {
    asm volatile("ldmatrix.sync.aligned.m8n8.x4.shared.b16 {%0,%1,%2,%3}, [%4];"
                 : "=r"(r[0]), "=r"(r[1]), "=r"(r[2]), "=r"(r[3]) : "r"(addr));
}
__device__ __forceinline__ void ldsm4t(uint32_t* r, uint32_t addr) {
    asm volatile("ldmatrix.sync.aligned.m8n8.x4.trans.shared.b16 {%0,%1,%2,%3}, [%4];"
                 : "=r"(r[0]), "=r"(r[1]), "=r"(r[2]), "=r"(r[3]) : "r"(addr));
}
__device__ __forceinline__ void mma_f16(float* c, const uint32_t* a,
                                        uint32_t b0, uint32_t b1) {
    asm volatile(
        "mma.sync.aligned.m16n8k16.row.col.f32.f16.f16.f32 "
        "{%0,%1,%2,%3}, {%4,%5,%6,%7}, {%8,%9}, {%0,%1,%2,%3};"
        : "+f"(c[0]), "+f"(c[1]), "+f"(c[2]), "+f"(c[3])
        : "r"(a[0]), "r"(a[1]), "r"(a[2]), "r"(a[3]), "r"(b0), "r"(b1));
}
#define CP16(dst, src) asm volatile("cp.async.cg.shared.global [%0], [%1], 16;" :: "r"(dst), "l"(src))
#define CP_COMMIT()    asm volatile("cp.async.commit_group;" ::: "memory")
#define CP_WAIT0()     asm volatile("cp.async.wait_group 0;" ::: "memory")
#define CP_WAIT1()     asm volatile("cp.async.wait_group 1;" ::: "memory")
#define CP_WAIT2()     asm volatile("cp.async.wait_group 2;" ::: "memory")

__device__ __forceinline__ uint32_t pack2h(float a, float b) {
    __half2 h = __floats2half2_rn(a, b);
    return *reinterpret_cast<uint32_t*>(&h);
}
__device__ __forceinline__ uint32_t h2ex2(uint32_t x) {
    uint32_t d;
    asm("ex2.approx.f16x2 %0, %1;" : "=r"(d) : "r"(x));
    return d;
}

#define LOG2E 1.4426950408889634f
#define MASK2 14426.950408889634f   // 10000 * log2(e)
#define ONES2 0x3C003C00u           // half2(1.0, 1.0)

// ---------------- merged prep kernel ------------------------------------------
// blocks [0, NBH): fp32->fp16 of Wqkv then Wo (flattened)
// blocks [NBH, NBH+NBX): 32x32 transpose+convert of x
#define NQ4 (3 * C_DIM * C_DIM / 4)     // 786432
#define NO4 (C_DIM * C_DIM / 4)         // 262144
#define NBH ((NQ4 + NO4) / 256)         // 4096
#define NBX ((S_LEN / 32) * (C_DIM / 32) * BATCH)  // 4608

__global__ void prep_kernel(const float* __restrict__ Wqkv,
                            const float* __restrict__ Wo,
                            const float* __restrict__ x) {
    int bx = blockIdx.x;
    int tid = threadIdx.x;
    if (bx < NBH) {
        int i = bx * 256 + tid;
        const float* src; __half* dst;
        if (i < NQ4) { src = Wqkv; dst = g_Wq; }
        else { i -= NQ4; src = Wo; dst = g_Wo; }
        float4 v = reinterpret_cast<const float4*>(src)[i];
        *reinterpret_cast<uint32_t*>(dst + (size_t)i * 4)     = pack2h(v.x, v.y);
        *reinterpret_cast<uint32_t*>(dst + (size_t)i * 4 + 2) = pack2h(v.z, v.w);
    } else {
        __shared__ float tile[32][33];
        int bi = bx - NBH;
        int gx = bi % (S_LEN / 32);
        int rem = bi / (S_LEN / 32);
        int gy = rem % (C_DIM / 32);
        int b  = rem / (C_DIM / 32);
        int t0 = gx * 32, c0 = gy * 32;
        int tx = tid & 31, ty = tid >> 5;
        for (int i = ty; i < 32; i += 8)
            tile[i][tx] = x[((size_t)b * C_DIM + c0 + i) * S_LEN + t0 + tx];
        __syncthreads();
        for (int i = ty; i < 32; i += 8) {
            size_t oi = ((size_t)b * S_LEN + t0 + i) * C_DIM + c0 + tx;
            g_x[oi] = __float2half_rn(tile[tx][i]);
        }
    }
}

// ---------------- mma.sync GEMM core: 256x128 tile, 512 thr, 4-stage ring ------
#define GP 72                          // pitch in halfs (144 B rows)
#define ABYTES (256 * 144)             // 36864
#define BBYTES (128 * 144)             // 18432
#define STBYTES (ABYTES + BBYTES)      // 55296

__device__ __forceinline__ void fill_async(
    uint32_t stage_s, int tid, int k0,
    const __half* A, const __half* B) {
#pragma unroll
    for (int i = tid; i < 2048; i += 512) {
        int r = i >> 3, c = (i & 7) * 16;
        CP16(stage_s + r * 144 + c, (const char*)(A + (size_t)r * C_DIM + k0) + c);
    }
#pragma unroll
    for (int i = tid; i < 1024; i += 512) {
        int r = i >> 3, c = (i & 7) * 16;
        CP16(stage_s + ABYTES + r * 144 + c, (const char*)(B + (size_t)r * C_DIM + k0) + c);
    }
    CP_COMMIT();
}

__device__ __forceinline__ void compute_stage(
    uint32_t st, int lane, int wm, int wn, float acc[4][4][4]) {
    uint32_t A_s = st, B_s = st + ABYTES;
    int ar = lane & 15, ach = (lane >> 4) * 8;
    int bg = lane >> 3, br = lane & 7;
    int brow = wn * 32 + (bg >> 1) * 8 + br;
    int bch = (bg & 1) * 8;
#pragma unroll
    for (int ks = 0; ks < 4; ks++) {
        uint32_t a[4][4], bb[2][4];
#pragma unroll
        for (int mi = 0; mi < 4; mi++)
            ldsm4(a[mi], A_s + ((wm * 64 + mi * 16 + ar) * GP + ks * 16 + ach) * 2);
#pragma unroll
        for (int nj = 0; nj < 2; nj++)
            ldsm4(bb[nj], B_s + ((brow + nj * 16) * GP + ks * 16 + bch) * 2);
#pragma unroll
        for (int mi = 0; mi < 4; mi++)
#pragma unroll
            for (int nj = 0; nj < 2; nj++) {
                mma_f16(acc[mi][nj * 2],     a[mi], bb[nj][0], bb[nj][1]);
                mma_f16(acc[mi][nj * 2 + 1], a[mi], bb[nj][2], bb[nj][3]);
            }
    }
}

__device__ __forceinline__ void gemm_body(
    uint32_t smb, int tid, float acc[4][4][4],
    const __half* A, const __half* B) {
    int lane = tid & 31, wid = tid >> 5;
    int wm = wid & 3, wn = wid >> 2;
    const int NC = C_DIM / 64;  // 16
    fill_async(smb, tid, 0, A, B);
    fill_async(smb + STBYTES, tid, 64, A, B);
    for (int ch = 0; ch < NC; ch++) {
        if (ch + 2 < NC) {
            fill_async(smb + ((ch + 2) & 3) * STBYTES, tid, (ch + 2) * 64, A, B);
            CP_WAIT2();
        } else if (ch + 2 == NC) {
            CP_WAIT1();
        } else {
            CP_WAIT0();
        }
        __syncthreads();
        compute_stage(smb + (ch & 3) * STBYTES, lane, wm, wn, acc);
    }
}

// ---------------- QKV projection (M = 256 tokens, N = 128 channels) ------------
__global__ __launch_bounds__(512, 1)
void qkv_tc(const float* __restrict__ bias) {
    extern __shared__ char sm[];
    uint32_t smb = smem_u32(sm);
    int tid = threadIdx.x;
    int b = blockIdx.z, n0 = blockIdx.x * 256, m0 = blockIdx.y * 128;

    float acc[4][4][4];
#pragma unroll
    for (int mi = 0; mi < 4; mi++)
#pragma unroll
        for (int ni = 0; ni < 4; ni++)
#pragma unroll
            for (int r = 0; r < 4; r++) acc[mi][ni][r] = 0.0f;

    gemm_body(smb, tid, acc,
              g_x + ((size_t)b * S_LEN + n0) * C_DIM,
              g_Wq + (size_t)m0 * C_DIM);

    int lane = tid & 31, wid = tid >> 5;
    int wm = wid & 3, wn = wid >> 2;
    int tc = lane & 3;
    int which = m0 >> 10;
    __half* dstb = (which == 0) ? g_q : (which == 1) ? g_k : g_v;
    float scale = (which == 0) ? (0.125f * LOG2E) : 1.0f;   // q in base-2 domain
    int mch0 = m0 + wn * 32;
    int head = (mch0 >> 6) & 15;
    int d0 = mch0 & 63;
    __half* base = dstb + ((size_t)(b * NH + head)) * S_LEN * HD;

    float bv0[4], bv1[4];
#pragma unroll
    for (int ni = 0; ni < 4; ni++) {
        bv0[ni] = bias[mch0 + ni * 8 + tc * 2];
        bv1[ni] = bias[mch0 + ni * 8 + tc * 2 + 1];
    }
#pragma unroll
    for (int mi = 0; mi < 4; mi++) {
#pragma unroll
        for (int rg = 0; rg < 2; rg++) {
            int t = n0 + wm * 64 + mi * 16 + (lane >> 2) + rg * 8;
            __half* rowp = base + (size_t)t * HD + d0 + tc * 2;
#pragma unroll
            for (int ni = 0; ni < 4; ni++) {
                uint32_t u = pack2h((acc[mi][ni][rg * 2 + 0] + bv0[ni]) * scale,
                                    (acc[mi][ni][rg * 2 + 1] + bv1[ni]) * scale);
                *reinterpret_cast<uint32_t*>(rowp + ni * 8) = u;
            }
        }
    }
}

// ---------------- Output projection (M = 256 co, N = 128 tokens) ---------------
__global__ __launch_bounds__(512, 1)
void out_tc(const float* __restrict__ bo, float* __restrict__ out) {
    extern __shared__ char sm[];
    uint32_t smb = smem_u32(sm);
    int tid = threadIdx.x;
    int b = blockIdx.z, m0 = blockIdx.y * 256, n0 = blockIdx.x * 128;

    float acc[4][4][4];
#pragma unroll
    for (int mi = 0; mi < 4; mi++)
#pragma unroll
        for (int ni = 0; ni < 4; ni++)
#pragma unroll
            for (int r = 0; r < 4; r++) acc[mi][ni][r] = 0.0f;

    gemm_body(smb, tid, acc,
              g_Wo + (size_t)m0 * C_DIM,
              g_z + ((size_t)b * S_LEN + n0) * C_DIM);

    int lane = tid & 31, wid = tid >> 5;
    int wm = wid & 3, wn = wid >> 2;
    int tc = lane & 3;
#pragma unroll
    for (int mi = 0; mi < 4; mi++) {
#pragma unroll
        for (int rg = 0; rg < 2; rg++) {
            int m = m0 + wm * 64 + mi * 16 + (lane >> 2) + rg * 8;
            float bv = bo[m];
            float* dst = out + ((size_t)b * C_DIM + m) * S_LEN;
#pragma unroll
            for (int ni = 0; ni < 4; ni++) {
                int t = n0 + wn * 32 + ni * 8 + tc * 2;
                float2 v = {acc[mi][ni][rg * 2 + 0] + bv,
                            acc[mi][ni][rg * 2 + 1] + bv};
                *reinterpret_cast<float2*>(dst + t) = v;
            }
        }
    }
}

// ---------------- Flash attention (R15 measured-best version) -------------------
#define AP 72
#define QBYTES   18432
#define KVTILE   9216
#define KVBUF    18432

__device__ __forceinline__ void fill_kv(
    uint32_t dst, int tid, int s0, const __half* k, const __half* v) {
#pragma unroll
    for (int i = tid; i < 512; i += 256) {
        int r = i >> 3, c = (i & 7) * 16;
        uint32_t so = r * 144 + c;
        size_t go = (size_t)(s0 + r) * HD;
        CP16(dst + so,          (const char*)(k + go) + c);
        CP16(dst + KVTILE + so, (const char*)(v + go) + c);
    }
    CP_COMMIT();
}

__global__ __launch_bounds__(256, 2)
void attn_tc() {
    extern __shared__ char sm[];
    uint32_t smb = smem_u32(sm);
    uint32_t Q_s  = smb;
    uint32_t KV_s = smb + QBYTES;

    int head = blockIdx.y, b = blockIdx.z;
    int tid = threadIdx.x, lane = tid & 31, wid = tid >> 5;
    int r0w = wid * 16;
    int g = lane >> 2, tc = lane & 3;

    size_t base = ((size_t)(b * NH + head)) * S_LEN * HD;
    const __half* qp = g_q + base;
    const __half* kp = g_k + base;
    const __half* vp = g_v + base;

    int ar = lane & 15, ach = (lane >> 4) * 8;
    int bg = lane >> 3, br = lane & 7;
    int krow_off = ((bg >> 1) * 8 + br) * AP + (bg & 1) * 8;
    int vrow = ((lane >> 3) & 1) * 8 + (lane & 7);
    int vcol = (lane >> 4) * 8;

    for (int rep = 0; rep < 2; rep++) {
        int qt = rep == 0 ? (17 - (int)blockIdx.x) : (int)blockIdx.x;
        int q0 = qt * 128;

#pragma unroll
        for (int i = tid; i < 1024; i += 256) {
            int r = i >> 3, c = (i & 7) * 16;
            CP16(Q_s + r * 144 + c, (const char*)(qp + (size_t)(q0 + r) * HD) + c);
        }
        CP_COMMIT();

        float o[8][4] = {};
        float mA = -1e30f, mB = -1e30f, lA = 0.0f, lB = 0.0f;

        int nkt = 2 * qt + 2;
        fill_kv(KV_s, tid, 0, kp, vp);
        fill_kv(KV_s + KVBUF, tid, 64, kp, vp);
        for (int kt = 0; kt < nkt; kt++) {
            int c0 = kt * 64;
            if (kt + 2 < nkt) {
                fill_kv(KV_s + ((kt + 2) & 3) * KVBUF, tid, (kt + 2) * 64, kp, vp);
                CP_WAIT2();
            } else if (kt + 2 == nkt) {
                CP_WAIT1();
            } else {
                CP_WAIT0();
            }
            __syncthreads();
            uint32_t K_s = KV_s + (kt & 3) * KVBUF;
            uint32_t V_s = K_s + KVTILE;

            // ---- S = Q K^T (log2 units) ----
            float s[8][4] = {};
#pragma unroll
            for (int kc = 0; kc < 4; kc++) {
                uint32_t qh[4], kk[4][4];
                ldsm4(qh, Q_s + ((r0w + ar) * AP + kc * 16 + ach) * 2);
#pragma unroll
                for (int np = 0; np < 4; np++)
                    ldsm4(kk[np], K_s + (np * 16 * AP + kc * 16 + krow_off) * 2);
#pragma unroll
                for (int np = 0; np < 4; np++) {
                    mma_f16(s[np * 2],     qh, kk[np][0], kk[np][1]);
                    mma_f16(s[np * 2 + 1], qh, kk[np][2], kk[np][3]);
                }
            }

            // ---- mask (register domain, base-2) ----
            if (c0 + 63 > q0 + r0w) {
                int rowA = q0 + r0w + g, rowB = rowA + 8;
#pragma unroll
                for (int nf = 0; nf < 8; nf++) {
                    int col = c0 + nf * 8 + tc * 2;
                    if (col     > rowA) s[nf][0] -= MASK2;
                    if (col + 1 > rowA) s[nf][1] -= MASK2;
                    if (col     > rowB) s[nf][2] -= MASK2;
                    if (col + 1 > rowB) s[nf][3] -= MASK2;
                }
            }

            // ---- running max (quad shuffles) ----
            float pmA = -1e30f, pmB = -1e30f;
#pragma unroll
            for (int nf = 0; nf < 8; nf++) {
                pmA = fmaxf(pmA, fmaxf(s[nf][0], s[nf][1]));
                pmB = fmaxf(pmB, fmaxf(s[nf][2], s[nf][3]));
            }
            pmA = fmaxf(pmA, __shfl_xor_sync(0xffffffffu, pmA, 1));
            pmA = fmaxf(pmA, __shfl_xor_sync(0xffffffffu, pmA, 2));
            pmB = fmaxf(pmB, __shfl_xor_sync(0xffffffffu, pmB, 1));
            pmB = fmaxf(pmB, __shfl_xor_sync(0xffffffffu, pmB, 2));
            float mnA = fmaxf(mA, pmA), mnB = fmaxf(mB, pmB);

            // ---- alpha rescale (skipped when running max unchanged) ----
            float alA = 1.0f, alB = 1.0f;
            if (__any_sync(0xffffffffu, (mnA > mA) || (mnB > mB))) {
                alA = exp2f(mA - mnA);
                alB = exp2f(mB - mnB);
#pragma unroll
                for (int nf = 0; nf < 8; nf++) {
                    o[nf][0] *= alA; o[nf][1] *= alA;
                    o[nf][2] *= alB; o[nf][3] *= alB;
                }
            }
            mA = mnA; mB = mnB;

            // ---- P = ex2(S - m) in fp16x2 regs ----
            uint32_t pu[8][2];
#pragma unroll
            for (int nf = 0; nf < 8; nf++) {
                pu[nf][0] = h2ex2(pack2h(s[nf][0] - mnA, s[nf][1] - mnA));
                pu[nf][1] = h2ex2(pack2h(s[nf][2] - mnB, s[nf][3] - mnB));
            }

            // ---- l-sum via ones-MMA + O += P V ----
            float lf[4] = {0.0f, 0.0f, 0.0f, 0.0f};
#pragma unroll
            for (int kc = 0; kc < 4; kc++) {
                uint32_t ph[4], vv[4][4];
                ph[0] = pu[2 * kc][0];
                ph[1] = pu[2 * kc][1];
                ph[2] = pu[2 * kc + 1][0];
                ph[3] = pu[2 * kc + 1][1];
                mma_f16(lf, ph, ONES2, ONES2);   // row-sums of P (quad-reduced)
#pragma unroll
                for (int np = 0; np < 4; np++)
                    ldsm4t(vv[np], V_s + ((kc * 16 + vrow) * AP + np * 16 + vcol) * 2);
#pragma unroll
                for (int np = 0; np < 4; np++) {
                    mma_f16(o[np * 2],     ph, vv[np][0], vv[np][1]);
                    mma_f16(o[np * 2 + 1], ph, vv[np][2], vv[np][3]);
                }
            }
            lA = lA * alA + lf[0];
            lB = lB * alB + lf[2];
        }

        // ---- epilogue: z = O / l, fp16 ----
        float liA = 1.0f / lA, liB = 1.0f / lB;
        int tA = q0 + r0w + g, tB = tA + 8;
#pragma unroll
        for (int nf = 0; nf < 8; nf++) {
            int d = nf * 8 + tc * 2;
            size_t ziA = ((size_t)b * S_LEN + tA) * C_DIM + head * HD + d;
            size_t ziB = ((size_t)b * S_LEN + tB) * C_DIM + head * HD + d;
            *reinterpret_cast<uint32_t*>(g_z + ziA) = pack2h(o[nf][0] * liA, o[nf][1] * liA);
            *reinterpret_cast<uint32_t*>(g_z + ziB) = pack2h(o[nf][2] * liB, o[nf][3] * liB);
        }
        __syncthreads();
    }
}

// ---------------------------------------------------------------------------

extern "C" void kernel_launch(void* const* d_in, const int* in_sizes, int n_in,
                              void* d_out, int out_size) {
    const float* x    = (const float*)d_in[0];
    const float* Wqkv = (const float*)d_in[1];
    const float* bqkv = (const float*)d_in[2];
    const float* Wo   = (const float*)d_in[3];
    const float* bo   = (const float*)d_in[4];
    float* out = (float*)d_out;

    prep_kernel<<<NBH + NBX, 256>>>(Wqkv, Wo, x);

    size_t gsmem = 4 * STBYTES;   // 221184
    cudaFuncSetAttribute(qkv_tc, cudaFuncAttributeMaxDynamicSharedMemorySize, (int)gsmem);
    cudaFuncSetAttribute(out_tc, cudaFuncAttributeMaxDynamicSharedMemorySize, (int)gsmem);

    dim3 gA(S_LEN / 256, 3 * C_DIM / 128, BATCH);   // (9, 24, 2)
    qkv_tc<<<gA, 512, gsmem>>>(bqkv);

    size_t asmem = QBYTES + 4 * KVBUF;   // 92160
    cudaFuncSetAttribute(attn_tc, cudaFuncAttributeMaxDynamicSharedMemorySize, (int)asmem);
    dim3 gB(9, NH, BATCH);
    attn_tc<<<gB, 256, asmem>>>();

    dim3 gC(S_LEN / 128, C_DIM / 256, BATCH);       // (18, 4, 2)
    out_tc<<<gC, 512, gsmem>>>(bo, out);
}